// round 9
// baseline (speedup 1.0000x reference)
#include <cuda_runtime.h>
#include <math.h>
#include <stdint.h>

#define NC 200000
#define NF 64
#define NH 128
#define NS 512

// ---- scratch ----
__device__ float    d_logits[NC];
__device__ float    d_w2k[NH];
__device__ uint32_t d_W1frag[NF * NH];  // W1 in tf32, MMA-fragment order
__device__ float    d_c2;
__device__ float    d_sums[NS];
__device__ float    d_sl[NS];
__device__ float    d_cntf[NS];

__device__ __forceinline__ uint32_t f2tf32(float v) {
    uint32_t u;
    asm("cvt.rna.tf32.f32 %0, %1;" : "=r"(u) : "f"(v));
    return u;
}

__device__ __forceinline__ void mma_tf32(float c[4], const uint32_t a[4],
                                         uint32_t b0, uint32_t b1) {
    asm volatile(
        "mma.sync.aligned.m16n8k8.row.col.f32.tf32.tf32.f32 "
        "{%0,%1,%2,%3}, {%4,%5,%6,%7}, {%8,%9}, {%0,%1,%2,%3};"
        : "+f"(c[0]), "+f"(c[1]), "+f"(c[2]), "+f"(c[3])
        : "r"(a[0]), "r"(a[1]), "r"(a[2]), "r"(a[3]), "r"(b0), "r"(b1));
}

// ---- prep: W1 frag pack, w2k fold, c2, accumulator init ----
__global__ void k_prep(const float* __restrict__ W1, const float* __restrict__ W2,
                       const float* __restrict__ b2, const float* __restrict__ kw) {
    int b = blockIdx.x;
    int tid = threadIdx.x;  // 128
    if (b < 16) {
        int j4 = tid >> 5, lane = tid & 31;
        int q = lane & 3, g = lane >> 2;
        int col = b * 8 + g;
        int r0 = 16 * j4 + q;
        uint4 v;
        v.x = f2tf32(W1[(r0 + 0) * NH + col]);
        v.y = f2tf32(W1[(r0 + 4) * NH + col]);
        v.z = f2tf32(W1[(r0 + 8) * NH + col]);
        v.w = f2tf32(W1[(r0 + 12) * NH + col]);
        ((uint4*)d_W1frag)[(b * 4 + j4) * 32 + lane] = v;
    } else if (b < 32) {
        int w = tid >> 5, l = tid & 31;
        int rbase = (b - 16) * 8 + w * 2;
#pragma unroll
        for (int rr = 0; rr < 2; rr++) {
            int h = rbase + rr;
            float s = W2[h * NH + l] * kw[l] + W2[h * NH + l + 32] * kw[l + 32] +
                      W2[h * NH + l + 64] * kw[l + 64] + W2[h * NH + l + 96] * kw[l + 96];
            for (int o = 16; o; o >>= 1) s += __shfl_xor_sync(0xffffffffu, s, o);
            if (l == 0) d_w2k[h] = s;
        }
    } else if (b < 36) {
        int i = (b - 32) * 128 + tid;
        d_sums[i] = 0.f; d_sl[i] = 0.f; d_cntf[i] = 0.f;
    } else {
        float c = (tid < NH) ? b2[tid] * kw[tid] : 0.f;
        for (int o = 16; o; o >>= 1) c += __shfl_xor_sync(0xffffffffu, c, o);
        __shared__ float red[4];
        if ((tid & 31) == 0) red[tid >> 5] = c;
        __syncthreads();
        if (tid == 0) d_c2 = red[0] + red[1] + red[2] + red[3];
    }
}

// ================== tf32 mma.sync MLP (per-part) ==================
#define FS 68
#define OFF_FEAT 0
#define OFF_B1   (128 * FS * 4)
#define OFF_WK   (OFF_B1 + 512)
#define SMEM_MLP (OFF_WK + 512)

__global__ void __launch_bounds__(256, 4) k_mlp(const float* __restrict__ feat,
                                                const float* __restrict__ b1,
                                                int cbase) {
    extern __shared__ char smem[];
    float* featS = (float*)(smem + OFF_FEAT);
    float* b1s   = (float*)(smem + OFF_B1);
    float* wks   = (float*)(smem + OFF_WK);

    int tid = threadIdx.x;
    int wid = tid >> 5, lane = tid & 31;
    int g = lane >> 2, q = lane & 3;
    int base = cbase + blockIdx.x * 128;

    for (int i = tid; i < 128 * 16; i += 256) {
        int row = i >> 4, f4 = i & 15;
        float4 v = make_float4(0.f, 0.f, 0.f, 0.f);
        int c = base + row;
        if (c < NC) v = *(const float4*)(feat + (size_t)c * NF + f4 * 4);
        *(float4*)(featS + row * FS + f4 * 4) = v;
    }
    if (tid < NH) { b1s[tid] = b1[tid]; wks[tid] = d_w2k[tid]; }
    __syncthreads();

    uint32_t a[8][4];
    int r0 = wid * 16 + g;
#pragma unroll
    for (int kt = 0; kt < 8; kt++) {
        int k0 = kt * 8;
        a[kt][0] = f2tf32(featS[r0 * FS + k0 + q]);
        a[kt][1] = f2tf32(featS[(r0 + 8) * FS + k0 + q]);
        a[kt][2] = f2tf32(featS[r0 * FS + k0 + q + 4]);
        a[kt][3] = f2tf32(featS[(r0 + 8) * FS + k0 + q + 4]);
    }

    const uint4* fragp = (const uint4*)d_W1frag + lane;
    float acc0 = 0.f, acc1 = 0.f;
#pragma unroll
    for (int nt = 0; nt < 16; nt++) {
        const uint4* fb = fragp + nt * 128;
        uint4 B0 = fb[0];
        uint4 B1 = fb[32];
        uint4 B2 = fb[64];
        uint4 B3 = fb[96];
        float c0[4] = {0.f, 0.f, 0.f, 0.f};
        mma_tf32(c0, a[0], B0.x, B0.y);
        mma_tf32(c0, a[1], B0.z, B0.w);
        mma_tf32(c0, a[2], B1.x, B1.y);
        mma_tf32(c0, a[3], B1.z, B1.w);
        mma_tf32(c0, a[4], B2.x, B2.y);
        mma_tf32(c0, a[5], B2.z, B2.w);
        mma_tf32(c0, a[6], B3.x, B3.y);
        mma_tf32(c0, a[7], B3.z, B3.w);
        int col0 = nt * 8 + 2 * q, col1 = col0 + 1;
        float bb0 = b1s[col0], bb1 = b1s[col1];
        float wk0 = wks[col0], wk1 = wks[col1];
        acc0 += fmaxf(c0[0] + bb0, 0.f) * wk0 + fmaxf(c0[1] + bb1, 0.f) * wk1;
        acc1 += fmaxf(c0[2] + bb0, 0.f) * wk0 + fmaxf(c0[3] + bb1, 0.f) * wk1;
    }

    float c2v = d_c2;
#pragma unroll
    for (int rh = 0; rh < 2; rh++) {
        float v = (rh == 0) ? acc0 : acc1;
        v += __shfl_xor_sync(0xffffffffu, v, 1);
        v += __shfl_xor_sync(0xffffffffu, v, 2);
        v += c2v;
        int c = base + wid * 16 + rh * 8 + g;
        if (c < NC && q == 0) d_logits[c] = v;
    }
}

// ---- fused denominator + numerator + count (per-part), warp-per-step ----
// shift = d_logits[0] (part 0 always completes first); lse = shift + log(sum).
#define CHUNK 2048
#define DTPB 256
__global__ void __launch_bounds__(DTPB) k_denom(const int* __restrict__ sel,
                                                const int* __restrict__ proof,
                                                int chunk0) {
    __shared__ float es[CHUNK];
    __shared__ float pvs[CHUNK];
    __shared__ float pcs[CHUNK];
    int tid = threadIdx.x;
    int w = tid >> 5, l = tid & 31;
    int base = (chunk0 + blockIdx.x) * CHUNK;
    float shift = d_logits[0];

    for (int i = tid; i < CHUNK; i += DTPB) {
        int n = base + i;
        float e = 0.f, pv = 0.f, pc = 0.f;
        if (n < NC) {
            float lg = d_logits[n];
            e = expf(lg - shift);
            if (proof[n]) { pv = lg; pc = 1.f; }
        }
        es[i] = e; pvs[i] = pv; pcs[i] = pc;
    }
    __syncthreads();

    bool fast = (base + CHUNK) <= NC;
    for (int si = 0; si < 8; si++) {
        int s = blockIdx.y * 64 + si * 8 + w;
        const int* mrow = sel + (size_t)s * NC + base;
        float ad = 0.f, an = 0.f, ac = 0.f;
        if (fast) {
            const int4* m4 = (const int4*)mrow;
#pragma unroll
            for (int j = 0; j < 16; j++) {
                int p = j * 32 + l;
                int4 m = m4[p];
                float4 e4 = *(const float4*)&es[p * 4];
                float4 v4 = *(const float4*)&pvs[p * 4];
                float4 q4 = *(const float4*)&pcs[p * 4];
                if (m.x) { ad += e4.x; an += v4.x; ac += q4.x; }
                if (m.y) { ad += e4.y; an += v4.y; ac += q4.y; }
                if (m.z) { ad += e4.z; an += v4.z; ac += q4.z; }
                if (m.w) { ad += e4.w; an += v4.w; ac += q4.w; }
            }
        } else {
            for (int j = 0; j < 16; j++) {
                int e0 = j * 128 + l * 4;
#pragma unroll
                for (int p = 0; p < 4; p++) {
                    int n = base + e0 + p;
                    if (n < NC && mrow[e0 + p]) {
                        ad += es[e0 + p]; an += pvs[e0 + p]; ac += pcs[e0 + p];
                    }
                }
            }
        }
        for (int o = 16; o; o >>= 1) {
            ad += __shfl_xor_sync(0xffffffffu, ad, o);
            an += __shfl_xor_sync(0xffffffffu, an, o);
            ac += __shfl_xor_sync(0xffffffffu, ac, o);
        }
        if (l == 0) {
            atomicAdd(&d_sums[s], ad);
            atomicAdd(&d_sl[s], an);
            atomicAdd(&d_cntf[s], ac);
        }
    }
}

// ---- final loss ----
__global__ void k_final(float* out) {
    float shift = d_logits[0];
    int t = threadIdx.x;  // 512
    float v = (shift + logf(d_sums[t])) - d_sl[t] / d_cntf[t];
    for (int o = 16; o; o >>= 1) v += __shfl_xor_sync(0xffffffffu, v, o);
    __shared__ float red[16];
    if ((t & 31) == 0) red[t >> 5] = v;
    __syncthreads();
    if (t == 0) {
        float tot = 0.f;
#pragma unroll
        for (int w = 0; w < 16; w++) tot += red[w];
        out[0] = tot / (float)NS;
    }
}

extern "C" void kernel_launch(void* const* d_in, const int* in_sizes, int n_in,
                              void* d_out, int out_size) {
    const float* feat = (const float*)d_in[0];
    const float* W1   = (const float*)d_in[1];
    const float* b1   = (const float*)d_in[2];
    const float* W2   = (const float*)d_in[3];
    const float* b2   = (const float*)d_in[4];
    const float* kw   = (const float*)d_in[5];
    const int*   sel  = (const int*)d_in[6];
    const int*   proof= (const int*)d_in[7];
    float* out = (float*)d_out;

    static cudaStream_t s2 = nullptr;
    static cudaEvent_t evM[4], evJ;
    if (!s2) {
        cudaStreamCreateWithFlags(&s2, cudaStreamNonBlocking);
        for (int i = 0; i < 4; i++) cudaEventCreateWithFlags(&evM[i], cudaEventDisableTiming);
        cudaEventCreateWithFlags(&evJ, cudaEventDisableTiming);
        cudaFuncSetAttribute(k_mlp, cudaFuncAttributeMaxDynamicSharedMemorySize, SMEM_MLP);
    }

    k_prep<<<37, 128>>>(W1, W2, b2, kw);

    // 4 chunk-aligned parts; mlp on main stream, matching denom part on s2.
    const int cb[5] = {0, 51200, 102400, 153600, 200000};
    for (int p = 0; p < 4; p++) {
        int n = cb[p + 1] - cb[p];
        k_mlp<<<(n + 127) / 128, 256, SMEM_MLP>>>(feat, b1, cb[p]);
        cudaEventRecord(evM[p], 0);
        cudaStreamWaitEvent(s2, evM[p], 0);
        dim3 dg((n + CHUNK - 1) / CHUNK, NS / 64);
        k_denom<<<dg, DTPB, 0, s2>>>(sel, proof, cb[p] / CHUNK);
    }
    cudaEventRecord(evJ, s2);
    cudaStreamWaitEvent(0, evJ, 0);
    k_final<<<1, NS>>>(out);
}

// round 10
// speedup vs baseline: 1.1738x; 1.1738x over previous
#include <cuda_runtime.h>
#include <math.h>
#include <stdint.h>

#define NC 200000
#define NF 64
#define NH 128
#define NS 512

// ---- scratch ----
__device__ float    d_logits[NC];
__device__ float    d_w2k[NH];
__device__ uint32_t d_W1frag[NF * NH];  // W1 in tf32, MMA-fragment order
__device__ float    d_c2;
__device__ float    d_sums[NS];
__device__ float    d_sl[NS];
__device__ float    d_cntf[NS];

__device__ __forceinline__ uint32_t f2tf32(float v) {
    uint32_t u;
    asm("cvt.rna.tf32.f32 %0, %1;" : "=r"(u) : "f"(v));
    return u;
}

__device__ __forceinline__ void mma_tf32(float c[4], const uint32_t a[4],
                                         uint32_t b0, uint32_t b1) {
    asm volatile(
        "mma.sync.aligned.m16n8k8.row.col.f32.tf32.tf32.f32 "
        "{%0,%1,%2,%3}, {%4,%5,%6,%7}, {%8,%9}, {%0,%1,%2,%3};"
        : "+f"(c[0]), "+f"(c[1]), "+f"(c[2]), "+f"(c[3])
        : "r"(a[0]), "r"(a[1]), "r"(a[2]), "r"(a[3]), "r"(b0), "r"(b1));
}

// ---- launch 0: prep (W1 frag pack, w2k fold, c2) ----
__global__ void k_prep(const float* __restrict__ W1, const float* __restrict__ W2,
                       const float* __restrict__ b2, const float* __restrict__ kw) {
    int b = blockIdx.x;
    int tid = threadIdx.x;  // 128
    if (b < 16) {
        int j4 = tid >> 5, lane = tid & 31;
        int q = lane & 3, g = lane >> 2;
        int col = b * 8 + g;
        int r0 = 16 * j4 + q;
        uint4 v;
        v.x = f2tf32(W1[(r0 + 0) * NH + col]);
        v.y = f2tf32(W1[(r0 + 4) * NH + col]);
        v.z = f2tf32(W1[(r0 + 8) * NH + col]);
        v.w = f2tf32(W1[(r0 + 12) * NH + col]);
        ((uint4*)d_W1frag)[(b * 4 + j4) * 32 + lane] = v;
    } else if (b < 32) {
        int w = tid >> 5, l = tid & 31;
        int rbase = (b - 16) * 8 + w * 2;
#pragma unroll
        for (int rr = 0; rr < 2; rr++) {
            int h = rbase + rr;
            float s = W2[h * NH + l] * kw[l] + W2[h * NH + l + 32] * kw[l + 32] +
                      W2[h * NH + l + 64] * kw[l + 64] + W2[h * NH + l + 96] * kw[l + 96];
            for (int o = 16; o; o >>= 1) s += __shfl_xor_sync(0xffffffffu, s, o);
            if (l == 0) d_w2k[h] = s;
        }
    } else {
        float c = (tid < NH) ? b2[tid] * kw[tid] : 0.f;
        for (int o = 16; o; o >>= 1) c += __shfl_xor_sync(0xffffffffu, c, o);
        __shared__ float red[4];
        if ((tid & 31) == 0) red[tid >> 5] = c;
        __syncthreads();
        if (tid == 0) d_c2 = red[0] + red[1] + red[2] + red[3];
    }
}

// ================== launch 1: tf32 mma.sync MLP (monolithic) ==================
#define FS 68
#define OFF_FEAT 0
#define OFF_B1   (128 * FS * 4)
#define OFF_WK   (OFF_B1 + 512)
#define SMEM_MLP (OFF_WK + 512)

__global__ void __launch_bounds__(256, 4) k_mlp(const float* __restrict__ feat,
                                                const float* __restrict__ b1) {
    extern __shared__ char smem[];
    float* featS = (float*)(smem + OFF_FEAT);
    float* b1s   = (float*)(smem + OFF_B1);
    float* wks   = (float*)(smem + OFF_WK);

    int tid = threadIdx.x;
    int wid = tid >> 5, lane = tid & 31;
    int g = lane >> 2, q = lane & 3;
    int base = blockIdx.x * 128;

    for (int i = tid; i < 128 * 16; i += 256) {
        int row = i >> 4, f4 = i & 15;
        float4 v = make_float4(0.f, 0.f, 0.f, 0.f);
        int c = base + row;
        if (c < NC) v = *(const float4*)(feat + (size_t)c * NF + f4 * 4);
        *(float4*)(featS + row * FS + f4 * 4) = v;
    }
    if (tid < NH) { b1s[tid] = b1[tid]; wks[tid] = d_w2k[tid]; }
    __syncthreads();

    uint32_t a[8][4];
    int r0 = wid * 16 + g;
#pragma unroll
    for (int kt = 0; kt < 8; kt++) {
        int k0 = kt * 8;
        a[kt][0] = f2tf32(featS[r0 * FS + k0 + q]);
        a[kt][1] = f2tf32(featS[(r0 + 8) * FS + k0 + q]);
        a[kt][2] = f2tf32(featS[r0 * FS + k0 + q + 4]);
        a[kt][3] = f2tf32(featS[(r0 + 8) * FS + k0 + q + 4]);
    }

    const uint4* fragp = (const uint4*)d_W1frag + lane;
    float acc0 = 0.f, acc1 = 0.f;
#pragma unroll
    for (int nt = 0; nt < 16; nt++) {
        const uint4* fb = fragp + nt * 128;
        uint4 B0 = fb[0];
        uint4 B1 = fb[32];
        uint4 B2 = fb[64];
        uint4 B3 = fb[96];
        float c0[4] = {0.f, 0.f, 0.f, 0.f};
        mma_tf32(c0, a[0], B0.x, B0.y);
        mma_tf32(c0, a[1], B0.z, B0.w);
        mma_tf32(c0, a[2], B1.x, B1.y);
        mma_tf32(c0, a[3], B1.z, B1.w);
        mma_tf32(c0, a[4], B2.x, B2.y);
        mma_tf32(c0, a[5], B2.z, B2.w);
        mma_tf32(c0, a[6], B3.x, B3.y);
        mma_tf32(c0, a[7], B3.z, B3.w);
        int col0 = nt * 8 + 2 * q, col1 = col0 + 1;
        float bb0 = b1s[col0], bb1 = b1s[col1];
        float wk0 = wks[col0], wk1 = wks[col1];
        acc0 += fmaxf(c0[0] + bb0, 0.f) * wk0 + fmaxf(c0[1] + bb1, 0.f) * wk1;
        acc1 += fmaxf(c0[2] + bb0, 0.f) * wk0 + fmaxf(c0[3] + bb1, 0.f) * wk1;
    }

    float c2v = d_c2;
#pragma unroll
    for (int rh = 0; rh < 2; rh++) {
        float v = (rh == 0) ? acc0 : acc1;
        v += __shfl_xor_sync(0xffffffffu, v, 1);
        v += __shfl_xor_sync(0xffffffffu, v, 2);
        v += c2v;
        int c = base + wid * 16 + rh * 8 + g;
        if (c < NC && q == 0) d_logits[c] = v;
    }
}

// ---- launch 2: init accumulators (also pads launch index so denom lands at 3) ----
__global__ void k_init() {
    int t = threadIdx.x;  // 512
    d_sums[t] = 0.f; d_sl[t] = 0.f; d_cntf[t] = 0.f;
}

// ---- launch 3: fused denominator + numerator + count, warp-per-step ----
// Inner loop: two explicit 8x int4 batches per step-row -> 8-deep MLP.
#define CHUNK 2048
#define DTPB 256
__global__ void __launch_bounds__(DTPB, 4) k_denom(const int* __restrict__ sel,
                                                   const int* __restrict__ proof) {
    __shared__ float es[CHUNK];
    __shared__ float pvs[CHUNK];
    __shared__ float pcs[CHUNK];
    int tid = threadIdx.x;
    int w = tid >> 5, l = tid & 31;
    int base = blockIdx.x * CHUNK;
    float shift = d_logits[0];

    for (int i = tid; i < CHUNK; i += DTPB) {
        int n = base + i;
        float e = 0.f, pv = 0.f, pc = 0.f;
        if (n < NC) {
            float lg = d_logits[n];
            e = expf(lg - shift);
            if (proof[n]) { pv = lg; pc = 1.f; }
        }
        es[i] = e; pvs[i] = pv; pcs[i] = pc;
    }
    __syncthreads();

    bool fast = (base + CHUNK) <= NC;
    for (int si = 0; si < 8; si++) {
        int s = blockIdx.y * 64 + si * 8 + w;
        const int* mrow = sel + (size_t)s * NC + base;
        float ad = 0.f, an = 0.f, ac = 0.f;
        if (fast) {
            const int4* m4 = (const int4*)mrow + l;
#pragma unroll
            for (int hh = 0; hh < 2; hh++) {
                int4 mb[8];
#pragma unroll
                for (int j = 0; j < 8; j++) mb[j] = m4[(hh * 8 + j) * 32];
#pragma unroll
                for (int j = 0; j < 8; j++) {
                    int p = ((hh * 8 + j) * 32 + l) * 4;
                    float4 e4 = *(const float4*)&es[p];
                    float4 v4 = *(const float4*)&pvs[p];
                    float4 q4 = *(const float4*)&pcs[p];
                    if (mb[j].x) { ad += e4.x; an += v4.x; ac += q4.x; }
                    if (mb[j].y) { ad += e4.y; an += v4.y; ac += q4.y; }
                    if (mb[j].z) { ad += e4.z; an += v4.z; ac += q4.z; }
                    if (mb[j].w) { ad += e4.w; an += v4.w; ac += q4.w; }
                }
            }
        } else {
            for (int j = 0; j < 16; j++) {
                int e0 = j * 128 + l * 4;
#pragma unroll
                for (int p = 0; p < 4; p++) {
                    int n = base + e0 + p;
                    if (n < NC && mrow[e0 + p]) {
                        ad += es[e0 + p]; an += pvs[e0 + p]; ac += pcs[e0 + p];
                    }
                }
            }
        }
        for (int o = 16; o; o >>= 1) {
            ad += __shfl_xor_sync(0xffffffffu, ad, o);
            an += __shfl_xor_sync(0xffffffffu, an, o);
            ac += __shfl_xor_sync(0xffffffffu, ac, o);
        }
        if (l == 0) {
            atomicAdd(&d_sums[s], ad);
            atomicAdd(&d_sl[s], an);
            atomicAdd(&d_cntf[s], ac);
        }
    }
}

// ---- launch 4: final loss ----
__global__ void k_final(float* out) {
    float shift = d_logits[0];
    int t = threadIdx.x;  // 512
    float v = (shift + logf(d_sums[t])) - d_sl[t] / d_cntf[t];
    for (int o = 16; o; o >>= 1) v += __shfl_xor_sync(0xffffffffu, v, o);
    __shared__ float red[16];
    if ((t & 31) == 0) red[t >> 5] = v;
    __syncthreads();
    if (t == 0) {
        float tot = 0.f;
#pragma unroll
        for (int w = 0; w < 16; w++) tot += red[w];
        out[0] = tot / (float)NS;
    }
}

extern "C" void kernel_launch(void* const* d_in, const int* in_sizes, int n_in,
                              void* d_out, int out_size) {
    const float* feat = (const float*)d_in[0];
    const float* W1   = (const float*)d_in[1];
    const float* b1   = (const float*)d_in[2];
    const float* W2   = (const float*)d_in[3];
    const float* b2   = (const float*)d_in[4];
    const float* kw   = (const float*)d_in[5];
    const int*   sel  = (const int*)d_in[6];
    const int*   proof= (const int*)d_in[7];
    float* out = (float*)d_out;

    static int smem_set = 0;
    if (!smem_set) {
        cudaFuncSetAttribute(k_mlp, cudaFuncAttributeMaxDynamicSharedMemorySize, SMEM_MLP);
        smem_set = 1;
    }

    k_prep<<<33, 128>>>(W1, W2, b2, kw);                   // 0
    k_mlp<<<(NC + 127) / 128, 256, SMEM_MLP>>>(feat, b1);  // 1
    k_init<<<1, 512>>>();                                  // 2
    dim3 dg((NC + CHUNK - 1) / CHUNK, NS / 64);
    k_denom<<<dg, DTPB>>>(sel, proof);                     // 3 <- ncu capture slot
    k_final<<<1, NS>>>(out);                               // 4
}